// round 3
// baseline (speedup 1.0000x reference)
#include <cuda_runtime.h>

#define HH 512
#define WW 512
#define PADK 5
#define TILE 32
#define PXn 8           // output pixels per thread in x
#define HALO 42         // TILE + 2*PADK
#define SSTR 43         // smem row stride (elements); odd => conflict-free under column-major lanes
#define PLANE (HALO * SSTR)

typedef unsigned long long ull;

// predicated packed tap: if (vr >= dst) { acc01 += v01; acc2g += v2g; }  (3 issues)
#define TAP(acc01, acc2g, vr, dst, v01, v2g)                          \
    asm("{ .reg .pred p;\n\t"                                         \
        "setp.ge.f32 p, %2, %3;\n\t"                                  \
        "@p add.rn.f32x2 %0, %0, %4;\n\t"                             \
        "@p add.rn.f32x2 %1, %1, %5; }"                               \
        : "+l"(acc01), "+l"(acc2g)                                    \
        : "f"(vr), "f"(dst), "l"(v01), "l"(v2g))

__global__ __launch_bounds__(128, 6)
void bokeh_kernel(const float* __restrict__ xin,
                  const float* __restrict__ lens,
                  const float* __restrict__ diskernel,
                  float* __restrict__ out)
{
    // packed SoA planes: sm01 = {s0,s1}, sm2g = {s2,g}, smr = r
    __shared__ ull   sm01[PLANE];
    __shared__ ull   sm2g[PLANE];
    __shared__ float smr [PLANE];
    __shared__ float sdist[121];

    const int b  = blockIdx.z;
    const int x0 = blockIdx.x * TILE;
    const int y0 = blockIdx.y * TILE;
    const int t  = threadIdx.x;

    if (t < 121) sdist[t] = diskernel[t];

    const float le = lens[b];
    const float* xb = xin + (size_t)b * 4 * HH * WW;

    // Stage halo tile: r, g, s=rgb*g per source pixel, edge-clamped.
    for (int idx = t; idx < HALO * HALO; idx += 128) {
        int ly = (idx * 1561) >> 16;          // exact idx/42 for idx < 1764
        int lx = idx - ly * HALO;
        int gy = min(max(y0 + ly - PADK, 0), HH - 1);
        int gx = min(max(x0 + lx - PADK, 0), WW - 1);
        int o = gy * WW + gx;
        float c0  = xb[o];
        float c1  = xb[HH * WW + o];
        float c2  = xb[2 * HH * WW + o];
        float dsp = xb[3 * HH * WW + o];
        float r = fminf(fabsf(dsp) * le, 5.0f);
        float g = 1.0f / ((3.14159265358979323846f * r) * r + 1.0f);
        int so = ly * SSTR + lx;
        ull p01, p2g;
        asm("mov.b64 %0, {%1, %2};" : "=l"(p01) : "f"(c0 * g), "f"(c1 * g));
        asm("mov.b64 %0, {%1, %2};" : "=l"(p2g) : "f"(c2 * g), "f"(g));
        sm01[so] = p01;
        sm2g[so] = p2g;
        smr [so] = r;
    }
    __syncthreads();

    // COLUMN-MAJOR lane mapping: warp lanes sweep rows (ty), not columns.
    // Bank index for LDS.64 subgroup = ty*43 mod 16 = ty*11 mod 16: all distinct.
    const int ty = t & 31;        // local output row   (0..31)
    const int tx = t >> 5;        // column-group       (0..3)
    const int cb = tx * PXn;      // local output col base (0,8,16,24)

    ull acc01[PXn], acc2g[PXn];
    #pragma unroll
    for (int p = 0; p < PXn; p++) { acc01[p] = 0ull; acc2g[p] = 0ull; }

    // half-width of the disk per kernel row: (i-5)^2 + (j-5)^2 <= 25 (exact int math)
    const int HWROW[11] = {0, 3, 4, 4, 4, 5, 4, 4, 4, 3, 0};

    #pragma unroll
    for (int i = 0; i < 11; i++) {
        const int hw  = HWROW[i];
        const int jlo = 5 - hw;
        const int jhi = 5 + hw;
        const int rb  = (ty + i) * SSTR + cb;
        const ull*   row01 = &sm01[rb];
        const ull*   row2g = &sm2g[rb];
        const float* rowr  = &smr [rb];

        // this row's distance thresholds (broadcast LDS -> registers)
        float dstv[11];
        #pragma unroll
        for (int j = 0; j < 11; j++) {
            if (j >= jlo && j <= jhi) dstv[j] = sdist[i * 11 + j];
        }

        // column-shared loads: one (v01,v2g,vr) triple serves up to PXn pixels
        #pragma unroll
        for (int q = jlo; q <= jhi + PXn - 1; q++) {
            ull   v01 = row01[q];
            ull   v2g = row2g[q];
            float vr  = rowr [q];
            #pragma unroll
            for (int p = 0; p < PXn; p++) {
                int j = q - p;
                if (j < jlo || j > jhi) continue;    // compile-time elided
                TAP(acc01[p], acc2g[p], vr, dstv[j], v01, v2g);
            }
        }
    }

    // normalize and write (den > 0 always: center tap dist=0, r>=0)
    const int gy = y0 + ty;
    const int gx = x0 + cb;
    float n0[PXn], n1[PXn], n2[PXn];
    #pragma unroll
    for (int p = 0; p < PXn; p++) {
        float s0  = __uint_as_float((unsigned)(acc01[p]));
        float s1  = __uint_as_float((unsigned)(acc01[p] >> 32));
        float s2  = __uint_as_float((unsigned)(acc2g[p]));
        float den = __uint_as_float((unsigned)(acc2g[p] >> 32));
        float inv = __fdividef(1.0f, den);
        n0[p] = s0 * inv;
        n1[p] = s1 * inv;
        n2[p] = s2 * inv;
    }

    size_t ob = ((size_t)(b * 3) * HH + gy) * WW + gx;
    #pragma unroll
    for (int v = 0; v < 2; v++) {
        float4 r0 = make_float4(n0[4*v], n0[4*v+1], n0[4*v+2], n0[4*v+3]);
        float4 r1 = make_float4(n1[4*v], n1[4*v+1], n1[4*v+2], n1[4*v+3]);
        float4 r2 = make_float4(n2[4*v], n2[4*v+1], n2[4*v+2], n2[4*v+3]);
        *reinterpret_cast<float4*>(&out[ob + 4*v])               = r0;
        *reinterpret_cast<float4*>(&out[ob + 4*v + HH * WW])     = r1;
        *reinterpret_cast<float4*>(&out[ob + 4*v + 2 * HH * WW]) = r2;
    }
}

extern "C" void kernel_launch(void* const* d_in, const int* in_sizes, int n_in,
                              void* d_out, int out_size)
{
    const float* x    = (const float*)d_in[0];   // (4,4,512,512)
    const float* lens = (const float*)d_in[1];   // (4,1)
    const float* disk = (const float*)d_in[2];   // (11,11)
    float* out = (float*)d_out;                  // (4,3,512,512)

    dim3 block(128, 1, 1);
    dim3 grid(WW / TILE, HH / TILE, 4);          // 16 x 16 x 4
    bokeh_kernel<<<grid, block>>>(x, lens, disk, out);
}